// round 1
// baseline (speedup 1.0000x reference)
#include <cuda_runtime.h>
#include <math.h>

#define NN 8192
#define DD 128
#define PP 4096
#define NT 64          // 8192 / 128 tiles per dimension
#define TILE 128

// ---- device scratch (no allocations allowed) ----
__device__ float    g_s[PP];                 // sim_self per person (fp32, like reference G entries)
__device__ float    g_cval[NT * NT * 2];     // per-tile top-2 candidate values
__device__ unsigned g_cidx[NT * NT * 2];     // per-tile top-2 candidate flat indices (i*N+j)

// merge top-2 list (w1>=w2) into (v1,x1,v2,x2)
__device__ __forceinline__ void merge2(float& v1, unsigned& x1, float& v2, unsigned& x2,
                                       float w1, unsigned y1, float w2, unsigned y2) {
    if (w1 > v1) {
        float    nv2 = (v1 > w2) ? v1 : w2;
        unsigned nx2 = (v1 > w2) ? x1 : y2;
        v2 = nv2; x2 = nx2;
        v1 = w1;  x1 = y1;
    } else if (w1 > v2) {
        v2 = w1; x2 = y1;
    }
}

// ---------------------------------------------------------------------------
// Kernel 1: sim_self[p] = dot(x[p], x[p+1]), double accumulate, store fp32.
// One warp per person.
// ---------------------------------------------------------------------------
__global__ void k_self(const float* __restrict__ x) {
    int gwarp = (blockIdx.x * blockDim.x + threadIdx.x) >> 5;
    int lane  = threadIdx.x & 31;
    if (gwarp >= PP) return;
    const float* a = x + (size_t)gwarp * DD;
    const float* b = a + DD;
    double s = 0.0;
#pragma unroll
    for (int t = 0; t < 4; t++) {
        int l = lane + 32 * t;
        s += (double)a[l] * (double)b[l];
    }
#pragma unroll
    for (int off = 16; off; off >>= 1)
        s += __shfl_down_sync(0xffffffffu, s, off);
    if (lane == 0) g_s[gwarp] = (float)s;
}

// ---------------------------------------------------------------------------
// Kernel 2: 128x128 fp32 tile of G = x x^T, upper-triangular tiles only,
// with a top-2(+index) epilogue per block written to the candidate buffer.
// Dynamic smem: 2 * 128 * 128 * 4 = 128 KB.
// ---------------------------------------------------------------------------
extern "C" __global__ void __launch_bounds__(256, 1)
k_gemm_top2(const float* __restrict__ x) {
    int r = blockIdx.y, c = blockIdx.x;
    int slot = (r * NT + c) * 2;
    if (r > c) {  // lower-triangular tile: write sentinels so the reducer can scan all slots
        if (threadIdx.x == 0 && threadIdx.y == 0) {
            g_cval[slot]     = -INFINITY; g_cidx[slot]     = 0u;
            g_cval[slot + 1] = -INFINITY; g_cidx[slot + 1] = 0u;
        }
        return;
    }

    extern __shared__ float smem[];
    float* sA = smem;                 // [k][m], k-major, conflict-free stores
    float* sB = smem + TILE * DD;

    const int tid = threadIdx.y * 16 + threadIdx.x;
    const int rowBase = r * TILE;
    const int colBase = c * TILE;

    // Load both tiles, transposing [m][k] -> [k][m]. Consecutive lanes write
    // consecutive m => conflict-free smem stores; global reads are strided but
    // x is L2-resident (4 MB), so this is cheap.
    for (int t = tid; t < TILE * (DD / 4); t += 256) {
        int m  = t & (TILE - 1);
        int kv = t >> 7;              // 0..31 float4 groups along k
        float4 va = *(const float4*)(x + (size_t)(rowBase + m) * DD + kv * 4);
        sA[(kv * 4 + 0) * TILE + m] = va.x;
        sA[(kv * 4 + 1) * TILE + m] = va.y;
        sA[(kv * 4 + 2) * TILE + m] = va.z;
        sA[(kv * 4 + 3) * TILE + m] = va.w;
        float4 vb = *(const float4*)(x + (size_t)(colBase + m) * DD + kv * 4);
        sB[(kv * 4 + 0) * TILE + m] = vb.x;
        sB[(kv * 4 + 1) * TILE + m] = vb.y;
        sB[(kv * 4 + 2) * TILE + m] = vb.z;
        sB[(kv * 4 + 3) * TILE + m] = vb.w;
    }
    __syncthreads();

    const int tm = threadIdx.y * 8;
    const int tn = threadIdx.x * 8;

    float acc[8][8];
#pragma unroll
    for (int u = 0; u < 8; u++)
#pragma unroll
        for (int v = 0; v < 8; v++) acc[u][v] = 0.f;

#pragma unroll 4
    for (int k = 0; k < DD; k++) {
        float4 a0 = *(const float4*)&sA[k * TILE + tm];
        float4 a1 = *(const float4*)&sA[k * TILE + tm + 4];
        float4 b0 = *(const float4*)&sB[k * TILE + tn];
        float4 b1 = *(const float4*)&sB[k * TILE + tn + 4];
        float a[8] = {a0.x, a0.y, a0.z, a0.w, a1.x, a1.y, a1.z, a1.w};
        float b[8] = {b0.x, b0.y, b0.z, b0.w, b1.x, b1.y, b1.z, b1.w};
#pragma unroll
        for (int u = 0; u < 8; u++)
#pragma unroll
            for (int v = 0; v < 8; v++)
                acc[u][v] = fmaf(a[u], b[v], acc[u][v]);
    }

    // per-thread top-2 over the 8x8 micro-tile (strict upper triangle only)
    float    v1 = -INFINITY, v2 = -INFINITY;
    unsigned x1 = 0u, x2 = 0u;
    const bool offdiag = (r < c);
#pragma unroll
    for (int u = 0; u < 8; u++) {
        int i = rowBase + tm + u;
#pragma unroll
        for (int v = 0; v < 8; v++) {
            int j = colBase + tn + v;
            if (offdiag || i < j) {
                float g = acc[u][v];
                unsigned flat = (unsigned)i * NN + (unsigned)j;
                if (g > v1)      { v2 = v1; x2 = x1; v1 = g; x1 = flat; }
                else if (g > v2) { v2 = g;  x2 = flat; }
            }
        }
    }

    // warp reduce top-2
#pragma unroll
    for (int off = 16; off; off >>= 1) {
        float    w1 = __shfl_down_sync(0xffffffffu, v1, off);
        unsigned y1 = __shfl_down_sync(0xffffffffu, x1, off);
        float    w2 = __shfl_down_sync(0xffffffffu, v2, off);
        unsigned y2 = __shfl_down_sync(0xffffffffu, x2, off);
        merge2(v1, x1, v2, x2, w1, y1, w2, y2);
    }

    __shared__ float    swv1[8], swv2[8];
    __shared__ unsigned swx1[8], swx2[8];
    int wid  = tid >> 5;
    int lane = tid & 31;
    if (lane == 0) { swv1[wid] = v1; swx1[wid] = x1; swv2[wid] = v2; swx2[wid] = x2; }
    __syncthreads();
    if (tid == 0) {
        float    bv1 = swv1[0], bv2 = swv2[0];
        unsigned bx1 = swx1[0], bx2 = swx2[0];
#pragma unroll
        for (int w = 1; w < 8; w++)
            merge2(bv1, bx1, bv2, bx2, swv1[w], swx1[w], swv2[w], swx2[w]);
        g_cval[slot]     = bv1; g_cidx[slot]     = bx1;
        g_cval[slot + 1] = bv2; g_cidx[slot + 1] = bx2;
    }
}

// ---------------------------------------------------------------------------
// Kernel 3: reduce candidates -> global top-2, refine the two dots exactly
// (double), then mean over p of sim_oth/sim_self. Single block.
// ---------------------------------------------------------------------------
__global__ void k_final(const float* __restrict__ x, float* __restrict__ out) {
    __shared__ float    swv1[8], swv2[8];
    __shared__ unsigned swx1[8], swx2[8];
    __shared__ unsigned sTop1, sTop2;
    __shared__ float    sd1, sd2;
    __shared__ double   ssum[256];

    const int tid  = threadIdx.x;
    const int lane = tid & 31;
    const int wid  = tid >> 5;

    // phase A: scan candidate buffer
    float    v1 = -INFINITY, v2 = -INFINITY;
    unsigned x1 = 0u, x2 = 0u;
    for (int t = tid; t < NT * NT * 2; t += 256)
        merge2(v1, x1, v2, x2, g_cval[t], g_cidx[t], -INFINITY, 0u);
#pragma unroll
    for (int off = 16; off; off >>= 1) {
        float    w1 = __shfl_down_sync(0xffffffffu, v1, off);
        unsigned y1 = __shfl_down_sync(0xffffffffu, x1, off);
        float    w2 = __shfl_down_sync(0xffffffffu, v2, off);
        unsigned y2 = __shfl_down_sync(0xffffffffu, x2, off);
        merge2(v1, x1, v2, x2, w1, y1, w2, y2);
    }
    if (lane == 0) { swv1[wid] = v1; swx1[wid] = x1; swv2[wid] = v2; swx2[wid] = x2; }
    __syncthreads();
    if (tid == 0) {
        float    bv1 = swv1[0], bv2 = swv2[0];
        unsigned bx1 = swx1[0], bx2 = swx2[0];
#pragma unroll
        for (int w = 1; w < 8; w++)
            merge2(bv1, bx1, bv2, bx2, swv1[w], swx1[w], swv2[w], swx2[w]);
        sTop1 = bx1; sTop2 = bx2;
    }
    __syncthreads();

    const unsigned f1 = sTop1, f2 = sTop2;
    const int i1 = (int)(f1 / NN), j1 = (int)(f1 % NN);
    const int i2 = (int)(f2 / NN), j2 = (int)(f2 % NN);

    // phase B: exact double-accumulated dots for the two winners (warps 0,1)
    if (tid < 64) {
        int which = tid >> 5;
        int ii = which ? i2 : i1;
        int jj = which ? j2 : j1;
        double s = 0.0;
#pragma unroll
        for (int t = 0; t < 4; t++) {
            int l = lane + 32 * t;
            s += (double)x[(size_t)ii * DD + l] * (double)x[(size_t)jj * DD + l];
        }
#pragma unroll
        for (int off = 16; off; off >>= 1)
            s += __shfl_down_sync(0xffffffffu, s, off);
        if (lane == 0) { if (which) sd2 = (float)s; else sd1 = (float)s; }
    }
    __syncthreads();

    const float v1f = sd1, v2f = sd2;
    const bool top1_self = (j1 == i1 + 1) && (i1 < PP);

    // phase C: mean over persons of sim_oth/sim_self
    double sum = 0.0;
    for (int p = tid; p < PP; p += 256) {
        float num   = (top1_self && p == i1) ? v2f : v1f;
        float ratio = num / g_s[p];
        sum += (double)ratio;
    }
    ssum[tid] = sum;
    __syncthreads();
    for (int s = 128; s; s >>= 1) {
        if (tid < s) ssum[tid] += ssum[tid + s];
        __syncthreads();
    }
    if (tid == 0) out[0] = (float)(ssum[0] / (double)PP);
}

// ---------------------------------------------------------------------------
extern "C" void kernel_launch(void* const* d_in, const int* in_sizes, int n_in,
                              void* d_out, int out_size) {
    const float* x = (const float*)d_in[0];
    float* out = (float*)d_out;

    // opt-in 128 KB dynamic smem for the tile kernel (idempotent, not a stream op)
    cudaFuncSetAttribute((const void*)k_gemm_top2,
                         cudaFuncAttributeMaxDynamicSharedMemorySize,
                         2 * TILE * DD * (int)sizeof(float));

    k_self<<<512, 256>>>(x);
    dim3 grid(NT, NT), block(16, 16);
    k_gemm_top2<<<grid, block, 2 * TILE * DD * sizeof(float)>>>(x);
    k_final<<<1, 256>>>(x, out);
}

// round 17
// speedup vs baseline: 3.2228x; 3.2228x over previous
#include <cuda_runtime.h>
#include <cuda_bf16.h>
#include <cstdint>
#include <math.h>

#define NN 8192
#define DD 128
#define PP 4096
#define NT 64            // 8192/128 tiles per dim
#define TILE 128
#define NPAIRS 2080      // NT*(NT+1)/2 upper-triangular tile pairs
#define NCAND (NPAIRS * 2)
#define PITCH 68         // smem row pitch in u32 (64 data + 4 pad, conflict-free)

// ---- device scratch ----
__device__ unsigned g_xb32[NN * 64];   // x in bf16, packed 2/word (2 MB)
__device__ float    g_s[PP];           // sim_self
__device__ float    g_cval[NCAND];     // per-tile top-2 values
__device__ unsigned g_cidx[NCAND];     // per-tile top-2 flat indices

__device__ __forceinline__ void mma16816(float* c, const unsigned* a, const unsigned* b) {
    asm volatile(
        "mma.sync.aligned.m16n8k16.row.col.f32.bf16.bf16.f32 "
        "{%0,%1,%2,%3}, {%4,%5,%6,%7}, {%8,%9}, {%0,%1,%2,%3};"
        : "+f"(c[0]), "+f"(c[1]), "+f"(c[2]), "+f"(c[3])
        : "r"(a[0]), "r"(a[1]), "r"(a[2]), "r"(a[3]), "r"(b[0]), "r"(b[1]));
}

__device__ __forceinline__ void merge2(float& v1, unsigned& x1, float& v2, unsigned& x2,
                                       float w1, unsigned y1, float w2, unsigned y2) {
    if (w1 > v1) {
        float    nv2 = (v1 > w2) ? v1 : w2;
        unsigned nx2 = (v1 > w2) ? x1 : y2;
        v2 = nv2; x2 = nx2;
        v1 = w1;  x1 = y1;
    } else if (w1 > v2) {
        v2 = w1; x2 = y1;
    }
}

__device__ __forceinline__ void ins4(float* tv, unsigned* tx, float v, unsigned xx) {
    if (v > tv[3]) {
        tv[3] = v; tx[3] = xx;
#pragma unroll
        for (int i = 3; i > 0; i--) {
            if (tv[i] > tv[i - 1]) {
                float tvs = tv[i]; tv[i] = tv[i - 1]; tv[i - 1] = tvs;
                unsigned txs = tx[i]; tx[i] = tx[i - 1]; tx[i - 1] = txs;
            }
        }
    }
}

// ---------------------------------------------------------------------------
// Kernel 0: convert x (fp32) -> bf16 pairs in g_xb32
// ---------------------------------------------------------------------------
__global__ void k_convert(const float* __restrict__ x) {
    int i = blockIdx.x * blockDim.x + threadIdx.x;
    if (i < NN * 64) {
        float2 f = ((const float2*)x)[i];
        __nv_bfloat162 h = __float22bfloat162_rn(f);
        g_xb32[i] = *(unsigned*)&h;
    }
}

// ---------------------------------------------------------------------------
// Kernel 1: sim_self[p] = dot(x[p], x[p+1]) (double accum, stored fp32)
// ---------------------------------------------------------------------------
__global__ void k_self(const float* __restrict__ x) {
    int w = (blockIdx.x * blockDim.x + threadIdx.x) >> 5;
    int lane = threadIdx.x & 31;
    if (w >= PP) return;
    const float4* a = (const float4*)(x + (size_t)w * DD);
    const float4* b = (const float4*)(x + (size_t)(w + 1) * DD);
    float4 av = a[lane];
    float4 bv = b[lane];
    double s = (double)av.x * bv.x + (double)av.y * bv.y +
               (double)av.z * bv.z + (double)av.w * bv.w;
#pragma unroll
    for (int off = 16; off; off >>= 1)
        s += __shfl_down_sync(0xffffffffu, s, off);
    if (lane == 0) g_s[w] = (float)s;
}

// ---------------------------------------------------------------------------
// Kernel 2: bf16 mma.sync 128x128 Gram tile per CTA over upper-tri tile pairs,
// top-2(+flat index) epilogue.
// 8 warps: warp (wid&1) -> 64-row half, (wid>>1) -> 32-col quarter.
// ---------------------------------------------------------------------------
__global__ __launch_bounds__(256, 1)
void k_search() {
    extern __shared__ unsigned smem[];
    unsigned* sA32 = smem;                  // 128 x PITCH u32
    unsigned* sB32 = smem + TILE * PITCH;   // 128 x PITCH u32
    __shared__ float    sv1[8], sv2[8];
    __shared__ unsigned sx1[8], sx2[8];

    const int tid = threadIdx.x;
    const int wid = tid >> 5;
    const int lane = tid & 31;

    // decode upper-triangular (r,c) from linear block id
    int t = blockIdx.x;
    int r = (int)((2 * NT + 1 - sqrtf((float)((2 * NT + 1) * (2 * NT + 1) - 8 * t))) * 0.5f);
    while ((r + 1) * NT - (((r + 1) * r) >> 1) <= t) r++;
    while (r * NT - ((r * (r - 1)) >> 1) > t) r--;
    int c = r + t - (r * NT - ((r * (r - 1)) >> 1));
    const int rowBase = r * TILE;
    const int colBase = c * TILE;

    // fill both tiles (coalesced u32 loads; padded-pitch smem stores)
    for (int idx = tid; idx < TILE * 64; idx += 256) {
        int m = idx >> 6;
        int kk = idx & 63;
        sA32[m * PITCH + kk] = g_xb32[(rowBase + m) * 64 + kk];
        sB32[m * PITCH + kk] = g_xb32[(colBase + m) * 64 + kk];
    }
    __syncthreads();

    const int q = lane >> 2;    // group id (0..7)
    const int rr = lane & 3;    // thread-in-group
    const int mrow = (wid & 1) * 64;
    const int ncol = (wid >> 1) * 32;

    float acc[4][4][4];
#pragma unroll
    for (int mi = 0; mi < 4; mi++)
#pragma unroll
        for (int ni = 0; ni < 4; ni++)
#pragma unroll
            for (int e = 0; e < 4; e++) acc[mi][ni][e] = 0.f;

#pragma unroll
    for (int ks = 0; ks < 8; ks++) {
        const int ku = ks * 8;
        unsigned af[4][4];
#pragma unroll
        for (int mi = 0; mi < 4; mi++) {
            int r0 = mrow + mi * 16 + q;
            af[mi][0] = sA32[r0 * PITCH + ku + rr];
            af[mi][1] = sA32[(r0 + 8) * PITCH + ku + rr];
            af[mi][2] = sA32[r0 * PITCH + ku + 4 + rr];
            af[mi][3] = sA32[(r0 + 8) * PITCH + ku + 4 + rr];
        }
        unsigned bfr[4][2];
#pragma unroll
        for (int ni = 0; ni < 4; ni++) {
            int n0 = ncol + ni * 8 + q;
            bfr[ni][0] = sB32[n0 * PITCH + ku + rr];
            bfr[ni][1] = sB32[n0 * PITCH + ku + 4 + rr];
        }
#pragma unroll
        for (int mi = 0; mi < 4; mi++)
#pragma unroll
            for (int ni = 0; ni < 4; ni++)
                mma16816(acc[mi][ni], af[mi], bfr[ni]);
    }

    // per-thread top-2 over this thread's 64 output elements (strict i<j)
    float    v1 = -INFINITY, v2 = -INFINITY;
    unsigned X1 = 0u, X2 = 0u;
#pragma unroll
    for (int mi = 0; mi < 4; mi++) {
        int gi0 = rowBase + mrow + mi * 16 + q;
#pragma unroll
        for (int ni = 0; ni < 4; ni++) {
            int gj0 = colBase + ncol + ni * 8 + 2 * rr;
#pragma unroll
            for (int e = 0; e < 4; e++) {
                int gi = gi0 + ((e >> 1) << 3);   // +8 for c2/c3
                int gj = gj0 + (e & 1);           // +1 for c1/c3
                if (gi < gj) {
                    float g = acc[mi][ni][e];
                    unsigned f = (unsigned)gi * NN + (unsigned)gj;
                    if (g > v1)      { v2 = v1; X2 = X1; v1 = g; X1 = f; }
                    else if (g > v2) { v2 = g;  X2 = f; }
                }
            }
        }
    }

    // warp top-2 reduce
#pragma unroll
    for (int off = 16; off; off >>= 1) {
        float    w1 = __shfl_down_sync(0xffffffffu, v1, off);
        unsigned y1 = __shfl_down_sync(0xffffffffu, X1, off);
        float    w2 = __shfl_down_sync(0xffffffffu, v2, off);
        unsigned y2 = __shfl_down_sync(0xffffffffu, X2, off);
        merge2(v1, X1, v2, X2, w1, y1, w2, y2);
    }
    if (lane == 0) { sv1[wid] = v1; sx1[wid] = X1; sv2[wid] = v2; sx2[wid] = X2; }
    __syncthreads();
    if (tid == 0) {
        float    bv1 = sv1[0], bv2 = sv2[0];
        unsigned bx1 = sx1[0], bx2 = sx2[0];
#pragma unroll
        for (int w = 1; w < 8; w++)
            merge2(bv1, bx1, bv2, bx2, sv1[w], sx1[w], sv2[w], sx2[w]);
        int slot = blockIdx.x * 2;
        g_cval[slot]     = bv1; g_cidx[slot]     = bx1;
        g_cval[slot + 1] = bv2; g_cidx[slot + 1] = bx2;
    }
}

// ---------------------------------------------------------------------------
// Kernel 3: global top-4 from candidates, exact double refinement of all 4,
// re-rank, then mean over persons of sim_oth/sim_self.
// ---------------------------------------------------------------------------
__global__ void k_final(const float* __restrict__ x, float* __restrict__ out) {
    __shared__ float    swv[8][4];
    __shared__ unsigned swx[8][4];
    __shared__ unsigned sIdx[4];
    __shared__ float    sRef[4];
    __shared__ float    sV1, sV2;
    __shared__ int      sTi, sTj;
    __shared__ double   ssum[256];

    const int tid  = threadIdx.x;
    const int lane = tid & 31;
    const int wid  = tid >> 5;

    // per-thread top-4 scan of candidate buffer
    float    tv[4] = {-INFINITY, -INFINITY, -INFINITY, -INFINITY};
    unsigned tx[4] = {0u, 0u, 0u, 0u};
    for (int t = tid; t < NCAND; t += 256)
        ins4(tv, tx, g_cval[t], g_cidx[t]);

    // warp top-4 reduce
#pragma unroll
    for (int off = 16; off; off >>= 1) {
#pragma unroll
        for (int e = 0; e < 4; e++) {
            float    wv = __shfl_down_sync(0xffffffffu, tv[e], off);
            unsigned wx = __shfl_down_sync(0xffffffffu, tx[e], off);
            ins4(tv, tx, wv, wx);
        }
    }
    if (lane == 0) {
#pragma unroll
        for (int e = 0; e < 4; e++) { swv[wid][e] = tv[e]; swx[wid][e] = tx[e]; }
    }
    __syncthreads();
    if (tid == 0) {
        float    fv[4] = {-INFINITY, -INFINITY, -INFINITY, -INFINITY};
        unsigned fx[4] = {0u, 0u, 0u, 0u};
        for (int w = 0; w < 8; w++)
            for (int e = 0; e < 4; e++)
                ins4(fv, fx, swv[w][e], swx[w][e]);
        for (int e = 0; e < 4; e++) sIdx[e] = fx[e];
    }
    __syncthreads();

    // exact double dots for all 4 candidates (warps 0..3)
    if (tid < 128) {
        int wch = tid >> 5;
        unsigned f = sIdx[wch];
        int ii = (int)(f / NN);
        int jj = (int)(f % NN);
        double s = 0.0;
#pragma unroll
        for (int t = 0; t < 4; t++) {
            int l = lane + 32 * t;
            s += (double)x[(size_t)ii * DD + l] * (double)x[(size_t)jj * DD + l];
        }
#pragma unroll
        for (int off = 16; off; off >>= 1)
            s += __shfl_down_sync(0xffffffffu, s, off);
        if (lane == 0) sRef[wch] = (float)s;
    }
    __syncthreads();

    // re-rank by refined values; pick top-2
    if (tid == 0) {
        float    rv[4];
        unsigned rx[4];
        for (int e = 0; e < 4; e++) { rv[e] = sRef[e]; rx[e] = sIdx[e]; }
        for (int a = 0; a < 3; a++)
            for (int b = a + 1; b < 4; b++)
                if (rv[b] > rv[a]) {
                    float tvs = rv[a]; rv[a] = rv[b]; rv[b] = tvs;
                    unsigned txs = rx[a]; rx[a] = rx[b]; rx[b] = txs;
                }
        sV1 = rv[0];
        sV2 = rv[1];
        sTi = (int)(rx[0] / NN);
        sTj = (int)(rx[0] % NN);
    }
    __syncthreads();

    const float v1f = sV1;
    const float v2f = sV2;
    const int   ti  = sTi;
    const int   tj  = sTj;
    const bool top1_self = (tj == ti + 1) && (ti < PP);

    double sum = 0.0;
    for (int p = tid; p < PP; p += 256) {
        float num   = (top1_self && p == ti) ? v2f : v1f;
        float ratio = num / g_s[p];
        sum += (double)ratio;
    }
    ssum[tid] = sum;
    __syncthreads();
    for (int s = 128; s; s >>= 1) {
        if (tid < s) ssum[tid] += ssum[tid + s];
        __syncthreads();
    }
    if (tid == 0) out[0] = (float)(ssum[0] / (double)PP);
}

// ---------------------------------------------------------------------------
extern "C" void kernel_launch(void* const* d_in, const int* in_sizes, int n_in,
                              void* d_out, int out_size) {
    const float* x = (const float*)d_in[0];
    float* out = (float*)d_out;

    cudaFuncSetAttribute((const void*)k_search,
                         cudaFuncAttributeMaxDynamicSharedMemorySize,
                         2 * TILE * PITCH * (int)sizeof(unsigned));

    k_convert<<<(NN * 64 + 255) / 256, 256>>>(x);
    k_self<<<512, 256>>>(x);
    k_search<<<NPAIRS, 256, 2 * TILE * PITCH * sizeof(unsigned)>>>();
    k_final<<<1, 256>>>(x, out);
}